// round 5
// baseline (speedup 1.0000x reference)
#include <cuda_runtime.h>

// AutogradLoss fused: loss = (x-y)^2, d_loss = 2(x-y), sqd_loss = 2*I (constant).
// Output layout: [loss (B*16) | d_loss (B*16) | sqd_loss (B*256)] floats.
// One kernel, one wave-friendly stream: 89% writes / 11% reads.
// Each block owns 64 samples: 256 f4 reads (x,y), 512 f4 loss/dloss writes,
// 4096 f4 hess writes. Hess pattern per thread is invariant across its 16 stores.

__global__ void __launch_bounds__(256) fused_kernel(
        const float4* __restrict__ x,
        const float4* __restrict__ y,
        float4* __restrict__ loss,
        float4* __restrict__ dloss,
        float4* __restrict__ sq,
        int n4_ld, long long n4_sq) {
    int tid = threadIdx.x;
    int i = blockIdx.x * 256 + tid;           // float4 index into x/y/loss/dloss

    // ---- Phase A: front-batch reads, compute, write loss + dloss ----
    if (i < n4_ld) {
        float4 a = __ldcs(&x[i]);
        float4 b = __ldcs(&y[i]);
        float dx = a.x - b.x, dy = a.y - b.y, dz = a.z - b.z, dw = a.w - b.w;
        float4 l = make_float4(dx * dx, dy * dy, dz * dz, dw * dw);
        float4 g = make_float4(2.f * dx, 2.f * dy, 2.f * dz, 2.f * dw);
        __stcs(&loss[i], l);
        __stcs(&dloss[i], g);
    }

    // ---- Phase B: hess writes. Block owns hess f4 range [blk*4096, +4096) ----
    // Within-sample f4 position = (base + k*256) & 63 = tid & 63 (4096, 256 ≡ 0 mod 64)
    // flat float offset s0 = pos*4; row = s0>>4; col0 = s0&15; elem e is 2 iff row==col0+e
    int pos = tid & 63;
    int s0 = pos << 2;
    int row = s0 >> 4;
    int col0 = s0 & 15;
    float4 v;
    v.x = (row == col0)     ? 2.0f : 0.0f;
    v.y = (row == col0 + 1) ? 2.0f : 0.0f;
    v.z = (row == col0 + 2) ? 2.0f : 0.0f;
    v.w = (row == col0 + 3) ? 2.0f : 0.0f;

    long long hbase = (long long)blockIdx.x * 4096 + tid;
    #pragma unroll
    for (int k = 0; k < 16; k++) {
        long long idx = hbase + (long long)k * 256;
        if (idx < n4_sq) {
            __stcs(&sq[idx], v);
        }
    }
}

extern "C" void kernel_launch(void* const* d_in, const int* in_sizes, int n_in,
                              void* d_out, int out_size) {
    const float* x = (const float*)d_in[0];
    const float* y = (const float*)d_in[1];
    float* out = (float*)d_out;

    long long bd = in_sizes[0];          // B*16 floats
    long long n4_ld = bd / 4;            // float4 count for loss / d_loss
    long long n4_sq = bd * 16 / 4;       // float4 count for sqd_loss

    float* loss  = out;
    float* dloss = out + bd;
    float* sq    = out + 2 * bd;

    int blocks = (int)((n4_ld + 255) / 256);
    fused_kernel<<<blocks, 256>>>((const float4*)x, (const float4*)y,
                                  (float4*)loss, (float4*)dloss, (float4*)sq,
                                  (int)n4_ld, n4_sq);
}

// round 6
// speedup vs baseline: 1.1088x; 1.1088x over previous
#include <cuda_runtime.h>

// AutogradLoss, serial two-kernel structure (fusion proven -11% DRAM eff in R5):
//   K1 loss_grad: read x,y -> write loss=(x-y)^2, dloss=2(x-y)   (268 MB, mixed)
//   K2 hess:      write sqd_loss = 2*I per sample                 (1.074 GB, pure write)
// Output layout: [loss (B*16) | d_loss (B*16) | sqd_loss (B*256)] floats.

// ---- K1: ILP=8, fully front-batched loads (256B read burst, then 256B write burst
//      per thread) to maximize same-direction DRAM bursts in the mixed phase. ----
__global__ void __launch_bounds__(256) loss_grad_kernel(
        const float4* __restrict__ x,
        const float4* __restrict__ y,
        float4* __restrict__ loss,
        float4* __restrict__ dloss,
        int n4) {
    int base = blockIdx.x * (256 * 8) + threadIdx.x;
    float4 a[8], b[8];
    // Phase 1: 16 outstanding loads
    #pragma unroll
    for (int j = 0; j < 8; j++) {
        int idx = base + j * 256;
        if (idx < n4) {
            a[j] = __ldcs(&x[idx]);
            b[j] = __ldcs(&y[idx]);
        }
    }
    // Phase 2: 16 stores
    #pragma unroll
    for (int j = 0; j < 8; j++) {
        int idx = base + j * 256;
        if (idx < n4) {
            float dx = a[j].x - b[j].x, dy = a[j].y - b[j].y;
            float dz = a[j].z - b[j].z, dw = a[j].w - b[j].w;
            __stcs(&loss[idx],  make_float4(dx * dx, dy * dy, dz * dz, dw * dw));
            __stcs(&dloss[idx], make_float4(2.f * dx, 2.f * dy, 2.f * dz, 2.f * dw));
        }
    }
}

// ---- K2: pure-write 2*I pattern, ILP=8 (R4 form, 92% DRAM / 7.73 TB/s). ----
// f4 index i: within-sample f4 pos = i&63; flat offset s0 = pos*4;
// row = s0>>4, col0 = s0&15; element e is 2.0 iff row == col0+e.
__global__ void __launch_bounds__(256) hess_kernel(float4* __restrict__ sq,
                                                   long long n4) {
    long long base = (long long)blockIdx.x * (256 * 8) + threadIdx.x;
    #pragma unroll
    for (int j = 0; j < 8; j++) {
        long long i = base + j * 256;
        if (i < n4) {
            int s0 = ((int)i & 63) << 2;
            int row = s0 >> 4;
            int col0 = s0 & 15;
            float4 v;
            v.x = (row == col0)     ? 2.0f : 0.0f;
            v.y = (row == col0 + 1) ? 2.0f : 0.0f;
            v.z = (row == col0 + 2) ? 2.0f : 0.0f;
            v.w = (row == col0 + 3) ? 2.0f : 0.0f;
            __stcs(&sq[i], v);
        }
    }
}

extern "C" void kernel_launch(void* const* d_in, const int* in_sizes, int n_in,
                              void* d_out, int out_size) {
    const float* x = (const float*)d_in[0];
    const float* y = (const float*)d_in[1];
    float* out = (float*)d_out;

    long long bd = in_sizes[0];          // B*16 floats
    long long n4_ld = bd / 4;            // float4 for loss / d_loss
    long long n4_sq = bd * 4;            // float4 for sqd_loss (bd*16/4)

    float* loss  = out;
    float* dloss = out + bd;
    float* sq    = out + 2 * bd;

    {
        long long per_block = 256LL * 8;
        int blocks = (int)((n4_ld + per_block - 1) / per_block);
        loss_grad_kernel<<<blocks, 256>>>((const float4*)x, (const float4*)y,
                                          (float4*)loss, (float4*)dloss,
                                          (int)n4_ld);
    }
    {
        long long per_block = 256LL * 8;
        int blocks = (int)((n4_sq + per_block - 1) / per_block);
        hess_kernel<<<blocks, 256>>>((float4*)sq, n4_sq);
    }
}